// round 4
// baseline (speedup 1.0000x reference)
#include <cuda_runtime.h>
#include <math.h>
#include <stdint.h>

// Problem constants (B, T, T) x (B, T, D) -> (B, T, D), fp32
#define NB 4
#define NT 4096
#define ND 256

#define BM 32      // t-rows per block tile
#define BK 32      // s-chunk
// BN = ND = 256 (full D per block)

__device__ float g_dinv[NB * NT];   // 1/sqrt(rowsum + eps)

// packed f32x2 helpers (sm_103a FFMA2 path — only reachable via PTX)
__device__ __forceinline__ unsigned long long pack2(float lo, float hi) {
    unsigned long long r;
    asm("mov.b64 %0, {%1, %2};" : "=l"(r) : "f"(lo), "f"(hi));
    return r;
}
__device__ __forceinline__ void unpack2(unsigned long long v, float& lo, float& hi) {
    asm("mov.b64 {%0, %1}, %2;" : "=f"(lo), "=f"(hi) : "l"(v));
}
__device__ __forceinline__ void fma2(unsigned long long& d,
                                     unsigned long long a, unsigned long long b) {
    asm("fma.rn.f32x2 %0, %1, %2, %0;" : "+l"(d) : "l"(a), "l"(b));
}

// ---------------------------------------------------------------------------
// Kernel 1: per-row sum of A -> dinv.  One block (256 thr) per row.
// ---------------------------------------------------------------------------
__global__ __launch_bounds__(256) void rowsum_kernel(const float* __restrict__ A)
{
    int row = blockIdx.x;                       // 0 .. NB*NT-1
    const float4* a4 = reinterpret_cast<const float4*>(A + (size_t)row * NT);
    float s = 0.f;
    #pragma unroll
    for (int i = 0; i < NT / 4 / 256; i++) {    // 4 iterations
        float4 v = a4[threadIdx.x + i * 256];
        s += (v.x + v.y) + (v.z + v.w);
    }
    #pragma unroll
    for (int o = 16; o > 0; o >>= 1) s += __shfl_xor_sync(0xffffffffu, s, o);
    __shared__ float ws[8];
    int lane = threadIdx.x & 31, w = threadIdx.x >> 5;
    if (lane == 0) ws[w] = s;
    __syncthreads();
    if (threadIdx.x == 0) {
        float tot = ws[0];
        #pragma unroll
        for (int i = 1; i < 8; i++) tot += ws[i];
        g_dinv[row] = 1.0f / sqrtf(tot + 1e-6f);
    }
}

// ---------------------------------------------------------------------------
// Kernel 2: causal tiled matmul, packed-f32x2 math.
//   out[b,t,d] = gate(t) * sqrt(0.5) * dinv[t] * sum_{s<=t} A[t,s]*dinv[s]*k[s,d]
// A tile stored PRE-BROADCAST: As2[k][row] = (a,a) packed in 8B, so the hot
// loop needs no packing movs. B pairs come free from contiguous fp32 rows.
// Block: 256 threads, tile BM=32 x ND=256, microtile 4x8 per thread.
// ---------------------------------------------------------------------------
__global__ __launch_bounds__(256) void causal_mm_kernel(
    const float* __restrict__ A, const float* __restrict__ K, float* __restrict__ out)
{
    int b  = blockIdx.y;
    int ti = (int)gridDim.x - 1 - (int)blockIdx.x;   // big tiles first
    int t0 = ti * BM;

    const float* Ab   = A   + (size_t)b * NT * NT;
    const float* Kb   = K   + (size_t)b * NT * ND;
    float*       Ob   = out + (size_t)b * NT * ND;
    const float* dinv = g_dinv + b * NT;

    __shared__ unsigned long long As2[BK][BM];  // (a*dinv_s, duplicated) [s][t]
    __shared__ float Bs[BK][ND];                // k[s,d]
    __shared__ float rowmax_s[BM];
    __shared__ float dinv_s[BK];                // dinv for current s-chunk

    int tid = threadIdx.x;
    int tr  = tid >> 5;                 // warp id: rows tr*4 .. tr*4+3
    int tc  = tid & 31;                 // cols tc*4 and 128+tc*4 (conflict-free)

    if (tid < BM) rowmax_s[tid] = 0.f;

    // A-load mapping: one float4 per thread (32 rows x 8 float4s)
    int arow = tid >> 3;                // 0..31
    int ac4  = (tid & 7) * 4;           // 0,4,...,28

    unsigned long long acc[4][4];       // 4 rows x 4 packed col-pairs
    const unsigned long long Z = pack2(0.f, 0.f);
    #pragma unroll
    for (int i = 0; i < 4; i++)
        #pragma unroll
        for (int j = 0; j < 4; j++) acc[i][j] = Z;

    int nK = ti + 1;                    // s-tiles 0..ti (diagonal last)
    for (int kk = 0; kk < nK; kk++) {
        int s0 = kk * BK;
        __syncthreads();
        if (tid < BK) dinv_s[tid] = dinv[s0 + tid];
        __syncthreads();

        // ---- load A tile, scale by dinv[s], mask on diagonal tile ----
        {
            int tg = t0 + arow;
            float4 av = *reinterpret_cast<const float4*>(
                Ab + (size_t)tg * NT + s0 + ac4);
            float v0 = av.x * dinv_s[ac4 + 0];
            float v1 = av.y * dinv_s[ac4 + 1];
            float v2 = av.z * dinv_s[ac4 + 2];
            float v3 = av.w * dinv_s[ac4 + 3];
            if (kk == nK - 1) {         // diagonal: keep s <= t only
                if (s0 + ac4 + 0 > tg) v0 = 0.f;
                if (s0 + ac4 + 1 > tg) v1 = 0.f;
                if (s0 + ac4 + 2 > tg) v2 = 0.f;
                if (s0 + ac4 + 3 > tg) v3 = 0.f;
            }
            As2[ac4 + 0][arow] = pack2(v0, v0);
            As2[ac4 + 1][arow] = pack2(v1, v1);
            As2[ac4 + 2][arow] = pack2(v2, v2);
            As2[ac4 + 3][arow] = pack2(v3, v3);
            // per-row max of |A*dinv_s| for the relation gate
            float m = fmaxf(fmaxf(fabsf(v0), fabsf(v1)),
                            fmaxf(fabsf(v2), fabsf(v3)));
            #pragma unroll
            for (int o = 4; o > 0; o >>= 1)      // reduce the 8 lanes of a row
                m = fmaxf(m, __shfl_xor_sync(0xffffffffu, m, o));
            if ((tid & 7) == 0)
                rowmax_s[arow] = fmaxf(rowmax_s[arow], m);
        }

        // ---- load K tile: 32 x 256 fp32 ----
        {
            #pragma unroll
            for (int i = 0; i < 8; i++) {
                int q = tid + i * 256;
                int r = q >> 6;
                int c = (q & 63) * 4;
                *reinterpret_cast<float4*>(&Bs[r][c]) =
                    *reinterpret_cast<const float4*>(
                        Kb + (size_t)(s0 + r) * ND + c);
            }
        }
        __syncthreads();

        // ---- compute: 4x8 outer products, 16 fma.f32x2 per k ----
        #pragma unroll
        for (int k = 0; k < BK; k++) {
            // 4 packed (a,a) values: warp-uniform address -> smem broadcast
            ulonglong2 a01 = *reinterpret_cast<const ulonglong2*>(&As2[k][tr * 4]);
            ulonglong2 a23 = *reinterpret_cast<const ulonglong2*>(&As2[k][tr * 4 + 2]);
            // 4 packed b pairs (b0,b1)(b2,b3)(b4,b5)(b6,b7)
            ulonglong2 bl = *reinterpret_cast<const ulonglong2*>(&Bs[k][tc * 4]);
            ulonglong2 bh = *reinterpret_cast<const ulonglong2*>(&Bs[k][128 + tc * 4]);
            unsigned long long ap[4] = {a01.x, a01.y, a23.x, a23.y};
            unsigned long long bp[4] = {bl.x, bl.y, bh.x, bh.y};
            #pragma unroll
            for (int i = 0; i < 4; i++) {
                fma2(acc[i][0], ap[i], bp[0]);
                fma2(acc[i][1], ap[i], bp[1]);
                fma2(acc[i][2], ap[i], bp[2]);
                fma2(acc[i][3], ap[i], bp[3]);
            }
        }
    }
    __syncthreads();   // rowmax_s complete

    const float SG = 0.70710678118654752440f;   // sqrt(0.5)
    #pragma unroll
    for (int i = 0; i < 4; i++) {
        int r = tr * 4 + i;
        int t = t0 + r;
        float dt = __ldg(dinv + t);
        float f  = (rowmax_s[r] * dt > 1e-9f) ? (SG * dt) : 0.f;
        float c0, c1, c2, c3, c4, c5, c6, c7;
        unpack2(acc[i][0], c0, c1);
        unpack2(acc[i][1], c2, c3);
        unpack2(acc[i][2], c4, c5);
        unpack2(acc[i][3], c6, c7);
        float4 lo = make_float4(c0 * f, c1 * f, c2 * f, c3 * f);
        float4 hi = make_float4(c4 * f, c5 * f, c6 * f, c7 * f);
        *reinterpret_cast<float4*>(Ob + (size_t)t * ND + tc * 4)       = lo;
        *reinterpret_cast<float4*>(Ob + (size_t)t * ND + 128 + tc * 4) = hi;
    }
}

// ---------------------------------------------------------------------------
extern "C" void kernel_launch(void* const* d_in, const int* in_sizes, int n_in,
                              void* d_out, int out_size)
{
    const float* A = (const float*)d_in[0];   // (4, 4096, 4096) fp32
    const float* K = (const float*)d_in[1];   // (4, 4096, 256)  fp32
    float* out = (float*)d_out;               // (4, 4096, 256)  fp32

    rowsum_kernel<<<NB * NT, 256>>>(A);

    dim3 grid(NT / BM, NB);
    causal_mm_kernel<<<grid, 256>>>(A, K, out);
}

// round 6
// speedup vs baseline: 1.5874x; 1.5874x over previous
#include <cuda_runtime.h>
#include <cuda_bf16.h>
#include <mma.h>
#include <math.h>
#include <stdint.h>

using namespace nvcuda;

#define NB 4
#define NT 4096
#define ND 256

#define BM 128            // t-rows per CTA
#define BN 128            // d-cols per CTA (2 CTAs cover D=256)
#define BK 64             // s-chunk
#define NTILES_M (NT / BM)    // 32

#define LDA 72            // A smem row stride in bf16 elems (64 + 8 pad = 144B)
#define LDB 72            // B smem row stride (per-n row, k contiguous)
#define LDE 136           // epilogue f32 smem row stride (544B, 16B-aligned)

__device__ __align__(16) float g_dinv[NB * NT];
__device__ __align__(16) __nv_bfloat16 g_Kt_hi[(size_t)NB * ND * NT];  // [b][d][s]
__device__ __align__(16) __nv_bfloat16 g_Kt_lo[(size_t)NB * ND * NT];

// ---- dynamic smem layout (bytes) ----
#define SM_AHI  0
#define SM_ALO  (SM_AHI + BM * LDA * 2)        // 18432
#define SM_BHI  (SM_ALO + BM * LDA * 2)        // 36864
#define SM_BLO  (SM_BHI + BN * LDB * 2)        // 55296
#define SM_END  (SM_BLO + BN * LDB * 2)        // 73728
#define SM_EPI  0                              // reuse A/B region: 128*136*4 = 69632
#define SM_TOTAL SM_END

// ---------------------------------------------------------------------------
// Kernel 1: rowsum -> dinv
// ---------------------------------------------------------------------------
__global__ __launch_bounds__(256) void rowsum_kernel(const float* __restrict__ A)
{
    int row = blockIdx.x;
    const float4* a4 = reinterpret_cast<const float4*>(A + (size_t)row * NT);
    float s = 0.f;
    #pragma unroll
    for (int i = 0; i < NT / 4 / 256; i++) {
        float4 v = a4[threadIdx.x + i * 256];
        s += (v.x + v.y) + (v.z + v.w);
    }
    #pragma unroll
    for (int o = 16; o > 0; o >>= 1) s += __shfl_xor_sync(0xffffffffu, s, o);
    __shared__ float ws[8];
    int lane = threadIdx.x & 31, w = threadIdx.x >> 5;
    if (lane == 0) ws[w] = s;
    __syncthreads();
    if (threadIdx.x == 0) {
        float tot = ws[0];
        #pragma unroll
        for (int i = 1; i < 8; i++) tot += ws[i];
        g_dinv[row] = 1.0f / sqrtf(tot + 1e-6f);
    }
}

// ---------------------------------------------------------------------------
// Kernel 2: K[b][s][d] -> Kt_hi/lo[b][d][s] bf16 split (32x32 smem transpose)
// ---------------------------------------------------------------------------
__global__ __launch_bounds__(256) void kt_kernel(const float* __restrict__ K)
{
    __shared__ float tile[32][33];
    int s0 = blockIdx.x * 32, d0 = blockIdx.y * 32, b = blockIdx.z;
    const float* Kb = K + (size_t)b * NT * ND;
    int tid = threadIdx.x;
    #pragma unroll
    for (int q = 0; q < 4; q++) {
        int idx = tid + q * 256;
        int r = idx >> 5, c = idx & 31;
        tile[r][c] = Kb[(size_t)(s0 + r) * ND + d0 + c];
    }
    __syncthreads();
    #pragma unroll
    for (int q = 0; q < 4; q++) {
        int idx = tid + q * 256;
        int dr = idx >> 5, sc = idx & 31;
        float v = tile[sc][dr];
        __nv_bfloat16 h = __float2bfloat16(v);
        __nv_bfloat16 l = __float2bfloat16(v - __bfloat162float(h));
        size_t off = (size_t)b * ND * NT + (size_t)(d0 + dr) * NT + s0 + sc;
        g_Kt_hi[off] = h;
        g_Kt_lo[off] = l;
    }
}

// ---------------------------------------------------------------------------
// Kernel 3: causal split-bf16 WMMA GEMM.
// CTA tile: 128(M) x 128(N), BK=64. Warps 4(M) x 2(N), warp tile 32x64.
// D = sum over k-tiles of (Ah+Al)(Bh+Bl) dropping Al*Bl.
// ---------------------------------------------------------------------------
__global__ __launch_bounds__(256) void causal_mm_wmma(
    const float* __restrict__ A, float* __restrict__ out)
{
    extern __shared__ char smem[];
    __nv_bfloat16* AsH = reinterpret_cast<__nv_bfloat16*>(smem + SM_AHI);
    __nv_bfloat16* AsL = reinterpret_cast<__nv_bfloat16*>(smem + SM_ALO);
    __nv_bfloat16* BsH = reinterpret_cast<__nv_bfloat16*>(smem + SM_BHI);
    __nv_bfloat16* BsL = reinterpret_cast<__nv_bfloat16*>(smem + SM_BLO);

    int tid = threadIdx.x, wid = tid >> 5;
    int b   = blockIdx.y;
    int ti  = NTILES_M - 1 - ((int)blockIdx.x >> 1);   // big tiles first
    int nh  = blockIdx.x & 1;                          // which 128-col half of D
    int t0  = ti * BM;
    int cn0 = nh * BN;

    const float* Ab   = A + (size_t)b * NT * NT;
    const float* dinv = g_dinv + b * NT;
    const __nv_bfloat16* KtH = g_Kt_hi + (size_t)b * ND * NT;
    const __nv_bfloat16* KtL = g_Kt_lo + (size_t)b * ND * NT;

    // warp tiling: 4 (M) x 2 (N)
    int wm = wid & 3;                // 0..3 -> m offset wm*32
    int wn = wid >> 2;               // 0..1 -> n offset wn*64

    wmma::fragment<wmma::accumulator, 16, 16, 16, float> facc[2][4];
    #pragma unroll
    for (int i = 0; i < 2; i++)
        #pragma unroll
        for (int j = 0; j < 4; j++) wmma::fill_fragment(facc[i][j], 0.0f);

    // A-conversion mapping: thread -> row ar (0..127), 32-col half
    int ar  = tid >> 1;
    int ac0 = (tid & 1) * 32;
    int t   = t0 + ar;
    float rmax = 0.f;

    // B-load mapping: thread -> n-row bn (0..127), 32-k half
    int bn  = tid >> 1;
    int bc0 = (tid & 1) * 32;

    int nK = 2 * (ti + 1);
    for (int kk = 0; kk < nK; kk++) {
        int s0 = kk * BK;
        __syncthreads();   // previous iteration's fragments consumed

        // ---- A tile: load f32, *dinv[s], causal mask, split hi/lo ----
        {
            const float4* Asrc = reinterpret_cast<const float4*>(Ab + (size_t)t * NT + s0 + ac0);
            const float4* Dsrc = reinterpret_cast<const float4*>(dinv + s0 + ac0);
            #pragma unroll
            for (int c = 0; c < 4; c++) {          // 8 values per chunk
                float4 a0 = Asrc[c * 2], a1 = Asrc[c * 2 + 1];
                float4 d0 = Dsrc[c * 2], d1 = Dsrc[c * 2 + 1];
                float v[8] = { a0.x * d0.x, a0.y * d0.y, a0.z * d0.z, a0.w * d0.w,
                               a1.x * d1.x, a1.y * d1.y, a1.z * d1.z, a1.w * d1.w };
                int sbase = s0 + ac0 + c * 8;
                #pragma unroll
                for (int e = 0; e < 8; e++) {
                    if (sbase + e > t) v[e] = 0.f;
                    rmax = fmaxf(rmax, fabsf(v[e]));
                }
                uint32_t h[4], l[4];
                #pragma unroll
                for (int p = 0; p < 4; p++) {
                    uint32_t hp;
                    asm("cvt.rn.bf16x2.f32 %0, %1, %2;"
                        : "=r"(hp) : "f"(v[2 * p + 1]), "f"(v[2 * p]));
                    float fe = __uint_as_float(hp << 16);
                    float fo = __uint_as_float(hp & 0xffff0000u);
                    uint32_t lp;
                    asm("cvt.rn.bf16x2.f32 %0, %1, %2;"
                        : "=r"(lp) : "f"(v[2 * p + 1] - fo), "f"(v[2 * p] - fe));
                    h[p] = hp; l[p] = lp;
                }
                int eoff = ar * LDA + ac0 + c * 8;          // elem offset, 16B aligned
                *reinterpret_cast<uint4*>(AsH + eoff) = make_uint4(h[0], h[1], h[2], h[3]);
                *reinterpret_cast<uint4*>(AsL + eoff) = make_uint4(l[0], l[1], l[2], l[3]);
            }
        }

        // ---- B tile: n-row bn (= global d cn0+bn), 32 k elems (64B) ----
        {
            const uint4* bh = reinterpret_cast<const uint4*>(KtH + (size_t)(cn0 + bn) * NT + s0 + bc0);
            const uint4* bl = reinterpret_cast<const uint4*>(KtL + (size_t)(cn0 + bn) * NT + s0 + bc0);
            int eoff = bn * LDB + bc0;
            #pragma unroll
            for (int j = 0; j < 4; j++) {               // 4 x 16B = 64B
                *reinterpret_cast<uint4*>(BsH + eoff + j * 8) = bh[j];
                *reinterpret_cast<uint4*>(BsL + eoff + j * 8) = bl[j];
            }
        }
        __syncthreads();

        // ---- WMMA: 4 k16-steps x (2 m-tiles x 4 n-tiles) x 3 split-MMAs ----
        #pragma unroll
        for (int ks = 0; ks < 4; ks++) {
            wmma::fragment<wmma::matrix_a, 16, 16, 16, __nv_bfloat16, wmma::row_major> faH[2], faL[2];
            #pragma unroll
            for (int i = 0; i < 2; i++) {
                const __nv_bfloat16* ap = AsH + (wm * 32 + i * 16) * LDA + ks * 16;
                const __nv_bfloat16* al = AsL + (wm * 32 + i * 16) * LDA + ks * 16;
                wmma::load_matrix_sync(faH[i], ap, LDA);
                wmma::load_matrix_sync(faL[i], al, LDA);
            }
            #pragma unroll
            for (int j = 0; j < 4; j++) {
                wmma::fragment<wmma::matrix_b, 16, 16, 16, __nv_bfloat16, wmma::col_major> fbH, fbL;
                const __nv_bfloat16* bp = BsH + (wn * 64 + j * 16) * LDB + ks * 16;
                const __nv_bfloat16* bl = BsL + (wn * 64 + j * 16) * LDB + ks * 16;
                wmma::load_matrix_sync(fbH, bp, LDB);
                wmma::load_matrix_sync(fbL, bl, LDB);
                #pragma unroll
                for (int i = 0; i < 2; i++) {
                    wmma::mma_sync(facc[i][j], faH[i], fbH, facc[i][j]);
                    wmma::mma_sync(facc[i][j], faH[i], fbL, facc[i][j]);
                    wmma::mma_sync(facc[i][j], faL[i], fbH, facc[i][j]);
                }
            }
        }
    }

    // rowmax: pair (2r, 2r+1) both end with the full-row max
    rmax = fmaxf(rmax, __shfl_xor_sync(0xffffffffu, rmax, 1));

    __syncthreads();   // all warps done with A/B smem -> reuse for epilogue
    float* Es = reinterpret_cast<float*>(smem + SM_EPI);
    #pragma unroll
    for (int i = 0; i < 2; i++)
        #pragma unroll
        for (int j = 0; j < 4; j++)
            wmma::store_matrix_sync(Es + (wm * 32 + i * 16) * LDE + wn * 64 + j * 16,
                                    facc[i][j], LDE, wmma::mem_row_major);
    __syncthreads();

    // scaled write-out: thread -> row ar, 64-col half
    {
        float dt = __ldg(dinv + t);
        float f  = (rmax * dt > 1e-9f) ? (0.70710678118654752440f * dt) : 0.f;
        int ch0 = (tid & 1) * 64;
        float* Orow = out + ((size_t)b * NT + t) * ND + cn0 + ch0;
        const float* Erow = Es + ar * LDE + ch0;
        #pragma unroll
        for (int q = 0; q < 16; q++) {
            float4 v = *reinterpret_cast<const float4*>(Erow + q * 4);
            float4 o = make_float4(v.x * f, v.y * f, v.z * f, v.w * f);
            *reinterpret_cast<float4*>(Orow + q * 4) = o;
        }
    }
}

// ---------------------------------------------------------------------------
extern "C" void kernel_launch(void* const* d_in, const int* in_sizes, int n_in,
                              void* d_out, int out_size)
{
    const float* A = (const float*)d_in[0];   // (4, 4096, 4096) fp32
    const float* K = (const float*)d_in[1];   // (4, 4096, 256)  fp32
    float* out = (float*)d_out;               // (4, 4096, 256)  fp32

    cudaFuncSetAttribute(causal_mm_wmma, cudaFuncAttributeMaxDynamicSharedMemorySize, SM_TOTAL);

    rowsum_kernel<<<NB * NT, 256>>>(A);

    dim3 gk(NT / 32, ND / 32, NB);
    kt_kernel<<<gk, 256>>>(K);

    dim3 gm(NTILES_M * 2, NB);
    causal_mm_wmma<<<gm, 256, SM_TOTAL>>>(A, out);
}